// round 11
// baseline (speedup 1.0000x reference)
#include <cuda_runtime.h>
#include <cuda_bf16.h>
#include <math.h>
#include <stdint.h>

#define BB 8
#define NQ 1024
#define NC 4096
#define DD 256
#define C1 25
#define CAP 2048          // compacted survivors cap (expected ~15 per row)
#define THRESH 1e-9f      // e = exp(s-max) threshold; dropped mass < 4096e-9

// ---------------- scratch (static device globals; no allocation) ----------------
__device__ float g_q_emb[(size_t)BB * NQ * DD];            //  8 MB fp32 (final gate)
__device__ float g_scores[(size_t)BB * NQ * NC];           // 134 MB
__device__ float g_copy[(size_t)BB * NQ * C1];
__device__ float g_cvec[(size_t)BB * NQ * DD];
// bf16 split operands
__device__ __nv_bfloat16 g_qh[(size_t)BB * NQ * DD];
__device__ __nv_bfloat16 g_ql[(size_t)BB * NQ * DD];
__device__ __nv_bfloat16 g_ch[(size_t)BB * NC * DD];
__device__ __nv_bfloat16 g_cl[(size_t)BB * NC * DD];
__device__ __nv_bfloat16 g_wth[DD * 2 * DD];               // W_rel^T [256][512]
__device__ __nv_bfloat16 g_wtl[DD * 2 * DD];

// ---------------- helpers ----------------
__device__ __forceinline__ uint32_t smem_u32(const void* p) {
    uint32_t a;
    asm("{ .reg .u64 t; cvta.to.shared.u64 t, %1; cvt.u32.u64 %0, t; }" : "=r"(a) : "l"(p));
    return a;
}
// SW64 swizzle for 64-byte rows
static __device__ __forceinline__ uint32_t swz64(uint32_t off) { return off ^ ((off >> 3) & 0x30); }

__device__ __forceinline__ unsigned pk2(float a, float b) {
    __nv_bfloat162 t = __floats2bfloat162_rn(a, b);
    return *reinterpret_cast<unsigned*>(&t);
}

__device__ __forceinline__ void ldmx4(uint32_t* r, uint32_t addr) {
    asm volatile("ldmatrix.sync.aligned.m8n8.x4.shared.b16 {%0,%1,%2,%3}, [%4];"
                 : "=r"(r[0]), "=r"(r[1]), "=r"(r[2]), "=r"(r[3]) : "r"(addr));
}
__device__ __forceinline__ void mma16816(float* d, const uint32_t* a, const uint32_t* b) {
    asm volatile(
        "mma.sync.aligned.m16n8k16.row.col.f32.bf16.bf16.f32 "
        "{%0,%1,%2,%3}, {%4,%5,%6,%7}, {%8,%9}, {%0,%1,%2,%3};"
        : "+f"(d[0]), "+f"(d[1]), "+f"(d[2]), "+f"(d[3])
        : "r"(a[0]), "r"(a[1]), "r"(a[2]), "r"(a[3]), "r"(b[0]), "r"(b[1]));
}
__device__ __forceinline__ void cp16(uint32_t dst, const void* src) {
    asm volatile("cp.async.cg.shared.global [%0], [%1], 16;" :: "r"(dst), "l"(src));
}
__device__ __forceinline__ void cp_commit() {
    asm volatile("cp.async.commit_group;");
}
template <int N>
__device__ __forceinline__ void cp_wait() {
    asm volatile("cp.async.wait_group %0;" :: "n"(N));
}

// async copy a bf16 tile [rows][32] from global (stride elems) into SW64 SMEM (64B rows)
__device__ __forceinline__ void copy_tile32(uint32_t dst, const __nv_bfloat16* src,
                                            size_t stride, int rows, int tid, int nthr) {
    const int tasks = rows * 4;
    for (int t = tid; t < tasks; t += nthr) {
        const int r = t >> 2, g = t & 3;
        cp16(dst + swz64((uint32_t)r * 64 + g * 16), src + (size_t)r * stride + g * 8);
    }
}

// stage layout (BK=32): 4 tiles of [rows<=128][32] bf16, 8KB each
#define S_AH 0
#define S_AL (8 * 1024)
#define S_BH (16 * 1024)
#define S_BL (24 * 1024)
#define STAGE (32 * 1024)
#define GM_SMEM (2 * STAGE + 1024)

// compute core: one BK=32 chunk; warp covers (MI*16) rows x 64 cols; bf16-3x
template <int MI>
__device__ __forceinline__ void mma_chunk32(uint32_t base, int wm, int wn, int lane,
                                            float acc[][8][4]) {
    const int a_r = wm * (MI * 16) + (lane & 15);
    const int a_cb = ((lane >> 4) & 1) * 16;
    const int b_r = wn * 64 + (lane & 7) + ((lane >> 4) & 1) * 8;
    const int b_cb = ((lane >> 3) & 1) * 16;
#pragma unroll
    for (int ks = 0; ks < 2; ks++) {
        uint32_t ah[MI][4], al[MI][4];
#pragma unroll
        for (int mi = 0; mi < MI; mi++) {
            const uint32_t oA = swz64((uint32_t)(a_r + mi * 16) * 64 + ks * 32 + a_cb);
            ldmx4(ah[mi], base + S_AH + oA);
            ldmx4(al[mi], base + S_AL + oA);
        }
#pragma unroll
        for (int p = 0; p < 4; p++) {
            const uint32_t oB = swz64((uint32_t)(b_r + p * 16) * 64 + ks * 32 + b_cb);
            uint32_t bh[4], bl[4];
            ldmx4(bh, base + S_BH + oB);
            ldmx4(bl, base + S_BL + oB);
#pragma unroll
            for (int t = 0; t < 2; t++) {
                const int ni = p * 2 + t;
#pragma unroll
                for (int mi = 0; mi < MI; mi++) {
                    mma16816(acc[mi][ni], ah[mi], bh + t * 2);
                    mma16816(acc[mi][ni], ah[mi], bl + t * 2);
                    mma16816(acc[mi][ni], al[mi], bh + t * 2);
                }
            }
        }
    }
}

// =====================================================================
// Kernel 0: W_rel [512][256] -> W^T bf16 hi/lo [256][512]
// =====================================================================
__global__ void wconv_kernel(const float* __restrict__ W) {
    __shared__ float t[32][33];
    const int k0 = blockIdx.x * 32, n0 = blockIdx.y * 32;
    const int tx = threadIdx.x, ty = threadIdx.y;
#pragma unroll
    for (int i = 0; i < 4; i++)
        t[ty + 8 * i][tx] = W[(size_t)(k0 + ty + 8 * i) * 256 + n0 + tx];
    __syncthreads();
#pragma unroll
    for (int i = 0; i < 4; i++) {
        const int n = n0 + ty + 8 * i, k = k0 + tx;
        const float x = t[tx][ty + 8 * i];
        const __nv_bfloat16 h = __float2bfloat16_rn(x);
        g_wth[(size_t)n * 512 + k] = h;
        g_wtl[(size_t)n * 512 + k] = __float2bfloat16_rn(x - __bfloat162float(h));
    }
}

// =====================================================================
// Kernel 1: rel_emb (BM=128, K=512 in 16 BK=32 chunks, 2-stage, 2 CTAs/SM)
// =====================================================================
__device__ __forceinline__ void relemb_loadA32(char* tpst, const float* H, const float* T,
                                               int kc, int m0, int tid) {
    const float* src = (kc < 8) ? H : T;
    const int cb = (kc * 32) & 255;
    for (int t = tid; t < 512; t += 256) {
        const int r = t >> 2, g = t & 3;
        const float* s = src + (size_t)(m0 + r) * 256 + cb + g * 8;
        float4 x0 = *(const float4*)s;
        float4 x1 = *(const float4*)(s + 4);
        float xs[8] = {x0.x, x0.y, x0.z, x0.w, x1.x, x1.y, x1.z, x1.w};
        float h[8], l[8];
#pragma unroll
        for (int i = 0; i < 8; i++) {
            h[i] = __bfloat162float(__float2bfloat16_rn(xs[i]));
            l[i] = xs[i] - h[i];
        }
        const uint32_t off = swz64((uint32_t)r * 64 + g * 16);
        *(uint4*)(tpst + S_AH + off) = make_uint4(pk2(h[0], h[1]), pk2(h[2], h[3]), pk2(h[4], h[5]), pk2(h[6], h[7]));
        *(uint4*)(tpst + S_AL + off) = make_uint4(pk2(l[0], l[1]), pk2(l[2], l[3]), pk2(l[4], l[5]), pk2(l[6], l[7]));
    }
}
__device__ __forceinline__ void relemb_loadB32(uint32_t basest, int n0, int kc, int tid) {
    copy_tile32(basest + S_BH, g_wth + (size_t)n0 * 512 + kc * 32, 512, 128, tid, 256);
    copy_tile32(basest + S_BL, g_wtl + (size_t)n0 * 512 + kc * 32, 512, 128, tid, 256);
    cp_commit();
}

__global__ __launch_bounds__(256, 2)
void relemb_mma(const float* __restrict__ H, const float* __restrict__ T,
                const float* __restrict__ bias, int is_c)
{
    extern __shared__ char dsm[];
    __shared__ float s_b[128];
    const uint32_t dbase = smem_u32(dsm);
    const uint32_t base = (dbase + 1023) & ~1023u;
    char* tp = dsm + (base - dbase);

    const int tid = threadIdx.x, wid = tid >> 5, lane = tid & 31;
    const int wm = wid >> 1, wn = wid & 1;
    const int n0 = blockIdx.x * 128, m0 = blockIdx.y * 128;
    if (tid < 128) s_b[tid] = bias[n0 + tid];

    float acc[2][8][4];
#pragma unroll
    for (int i = 0; i < 2; i++)
#pragma unroll
        for (int j = 0; j < 8; j++)
#pragma unroll
            for (int q = 0; q < 4; q++) acc[i][j][q] = 0.f;

    relemb_loadA32(tp, H, T, 0, m0, tid);
    relemb_loadB32(base, n0, 0, tid);
    for (int kc = 0; kc < 16; kc++) {
        const uint32_t cur = (kc & 1) * STAGE;
        const uint32_t nxt = cur ^ STAGE;
        if (kc < 15) {
            relemb_loadA32(tp + nxt, H, T, kc + 1, m0, tid);
            relemb_loadB32(base + nxt, n0, kc + 1, tid);
            cp_wait<1>();
        } else {
            cp_wait<0>();
        }
        __syncthreads();
        mma_chunk32<2>(base + cur, wm, wn, lane, acc);
        __syncthreads();
    }

    // epilogue
    const int cbase = wn * 64 + (lane & 3) * 2;
    __nv_bfloat16* dh = is_c ? g_ch : g_qh;
    __nv_bfloat16* dl = is_c ? g_cl : g_ql;
#pragma unroll
    for (int mi = 0; mi < 2; mi++) {
        const int r = m0 + wm * 32 + mi * 16 + (lane >> 2);
#pragma unroll
        for (int ni = 0; ni < 8; ni++) {
            const int c = n0 + cbase + ni * 8;
            const float b0 = s_b[c - n0], b1 = s_b[c - n0 + 1];
#pragma unroll
            for (int hh = 0; hh < 2; hh++) {
                const int row = r + hh * 8;
                const float v0 = acc[mi][ni][hh * 2 + 0] + b0;
                const float v1 = acc[mi][ni][hh * 2 + 1] + b1;
                const float h0 = __bfloat162float(__float2bfloat16_rn(v0));
                const float h1 = __bfloat162float(__float2bfloat16_rn(v1));
                *(unsigned*)(dh + (size_t)row * 256 + c) = pk2(h0, h1);
                *(unsigned*)(dl + (size_t)row * 256 + c) = pk2(v0 - h0, v1 - h1);
                if (!is_c)
                    *(float2*)(g_q_emb + (size_t)row * 256 + c) = make_float2(v0, v1);
            }
        }
    }
}

// =====================================================================
// Kernel 2: scores = (Qe @ Ce^T) * mask (BM=128, 8 BK=32 chunks, 2-stage,
//           2 CTAs/SM)
// =====================================================================
__global__ __launch_bounds__(256, 2)
void scores_mma(const float* __restrict__ mask)
{
    extern __shared__ char dsm[];
    __shared__ float s_msk[128];
    const uint32_t dbase = smem_u32(dsm);
    const uint32_t base = (dbase + 1023) & ~1023u;

    const int tid = threadIdx.x, wid = tid >> 5, lane = tid & 31;
    const int wm = wid >> 1, wn = wid & 1;
    const int n0 = blockIdx.x * 128, m0 = blockIdx.y * 128, b = blockIdx.z;
    if (tid < 128) s_msk[tid] = mask[(size_t)b * NC + n0 + tid];

    const __nv_bfloat16* qh = g_qh + ((size_t)b * NQ + m0) * 256;
    const __nv_bfloat16* ql = g_ql + ((size_t)b * NQ + m0) * 256;
    const __nv_bfloat16* ch = g_ch + ((size_t)b * NC + n0) * 256;
    const __nv_bfloat16* cl = g_cl + ((size_t)b * NC + n0) * 256;

    float acc[2][8][4];
#pragma unroll
    for (int i = 0; i < 2; i++)
#pragma unroll
        for (int j = 0; j < 8; j++)
#pragma unroll
            for (int q = 0; q < 4; q++) acc[i][j][q] = 0.f;

    // prefetch chunk 0
    copy_tile32(base + S_AH, qh, 256, 128, tid, 256);
    copy_tile32(base + S_AL, ql, 256, 128, tid, 256);
    copy_tile32(base + S_BH, ch, 256, 128, tid, 256);
    copy_tile32(base + S_BL, cl, 256, 128, tid, 256);
    cp_commit();
    for (int kc = 0; kc < 8; kc++) {
        const uint32_t cur = (kc & 1) * STAGE;
        const uint32_t nxt = cur ^ STAGE;
        if (kc < 7) {
            const int k1 = (kc + 1) * 32;
            copy_tile32(base + nxt + S_AH, qh + k1, 256, 128, tid, 256);
            copy_tile32(base + nxt + S_AL, ql + k1, 256, 128, tid, 256);
            copy_tile32(base + nxt + S_BH, ch + k1, 256, 128, tid, 256);
            copy_tile32(base + nxt + S_BL, cl + k1, 256, 128, tid, 256);
            cp_commit();
            cp_wait<1>();
        } else {
            cp_wait<0>();
        }
        __syncthreads();
        mma_chunk32<2>(base + cur, wm, wn, lane, acc);
        __syncthreads();
    }

    const int cbase = wn * 64 + (lane & 3) * 2;
#pragma unroll
    for (int mi = 0; mi < 2; mi++) {
        const int r = m0 + wm * 32 + mi * 16 + (lane >> 2);
#pragma unroll
        for (int ni = 0; ni < 8; ni++) {
            const int cl_ = cbase + ni * 8;
            const float mv0 = s_msk[cl_], mv1 = s_msk[cl_ + 1];
            float* p = g_scores + ((size_t)b * NQ + r) * NC + n0 + cl_;
            *(float2*)p = make_float2(acc[mi][ni][0] * mv0, acc[mi][ni][1] * mv1);
            *(float2*)(p + (size_t)8 * NC) = make_float2(acc[mi][ni][2] * mv0, acc[mi][ni][3] * mv1);
        }
    }
}

// =====================================================================
// Kernel 3: fused row softmax stats + class bins + SPARSE context_vec
// =====================================================================
__global__ __launch_bounds__(256)
void reduce_cvec_kernel(const int* __restrict__ labels)
{
    const int q = blockIdx.x, b = blockIdx.y;
    const size_t rowoff = ((size_t)b * NQ + q) * NC;
    const float* __restrict__ srow = g_scores + rowoff;
    const int* __restrict__ lab = labels + (size_t)b * NC;
    const int tid = threadIdx.x;

    __shared__ float red[256];
    __shared__ float bins[C1];
    __shared__ float total_sh;
    __shared__ int s_idx[CAP];
    __shared__ float s_e[CAP];
    __shared__ int s_cnt;

    float4 vals[4];
    float m = -INFINITY;
#pragma unroll
    for (int i = 0; i < 4; i++) {
        vals[i] = *(const float4*)(srow + (size_t)(i * 256 + tid) * 4);
        m = fmaxf(m, fmaxf(fmaxf(vals[i].x, vals[i].y), fmaxf(vals[i].z, vals[i].w)));
    }
    red[tid] = m;
    __syncthreads();
    for (int s = 128; s > 0; s >>= 1) {
        if (tid < s) red[tid] = fmaxf(red[tid], red[tid + s]);
        __syncthreads();
    }
    m = red[0];

    if (tid < C1) bins[tid] = 0.f;
    if (tid == 0) s_cnt = 0;
    __syncthreads();
#pragma unroll
    for (int i = 0; i < 4; i++) {
        const int bpos = (i * 256 + tid) * 4;
        int4 lb = *(const int4*)(lab + bpos);
        float e0 = __expf(vals[i].x - m), e1 = __expf(vals[i].y - m);
        float e2 = __expf(vals[i].z - m), e3 = __expf(vals[i].w - m);
        atomicAdd(&bins[lb.x], e0);
        atomicAdd(&bins[lb.y], e1);
        atomicAdd(&bins[lb.z], e2);
        atomicAdd(&bins[lb.w], e3);
        float ee[4] = {e0, e1, e2, e3};
#pragma unroll
        for (int c = 0; c < 4; c++) {
            if (ee[c] > THRESH) {
                int p = atomicAdd(&s_cnt, 1);
                if (p < CAP) { s_idx[p] = bpos + c; s_e[p] = ee[c]; }
            }
        }
    }
    __syncthreads();
    if (tid == 0) {
        float t = 0.f;
        for (int c = 0; c < C1; c++) t += bins[c];
        total_sh = t;
    }
    __syncthreads();

    // sparse context vector: d = tid
    {
        const __nv_bfloat16* chb = g_ch + (size_t)b * NC * DD;
        const __nv_bfloat16* clb = g_cl + (size_t)b * NC * DD;
        const int cnt = (s_cnt < CAP) ? s_cnt : CAP;
        float acc = 0.f;
        for (int i = 0; i < cnt; i++) {
            const size_t joff = (size_t)s_idx[i] * DD + tid;
            acc += s_e[i] * (__bfloat162float(chb[joff]) + __bfloat162float(clb[joff]));
        }
        g_cvec[((size_t)b * NQ + q) * DD + tid] = acc / total_sh;
    }

    if (tid < C1) {
        g_copy[((size_t)b * NQ + q) * C1 + tid] = __logf(bins[tid]) - __logf(total_sh);
    }
}

// =====================================================================
// Kernel 4: epilogue — gen log_softmax, gate, combine
// =====================================================================
__device__ __forceinline__ float softplus_f(float z) {
    return (z > 20.f) ? z : log1pf(__expf(z));
}

__global__ __launch_bounds__(256)
void final_kernel(const float* __restrict__ Wgen, const float* __restrict__ bgen,
                  const float* __restrict__ Wcp, const float* __restrict__ bcp,
                  float* __restrict__ out)
{
    __shared__ float wg[DD * C1];
    __shared__ float wcp[2 * DD];
    __shared__ float qsh[8][DD];
    const int tid = threadIdx.x;
    for (int i = tid; i < DD * C1; i += 256) wg[i] = Wgen[i];
    for (int i = tid; i < 2 * DD; i += 256) wcp[i] = Wcp[i];
    __syncthreads();

    const int w = tid >> 5, l = tid & 31;
    const int row = blockIdx.x * 8 + w;
    const float* __restrict__ qe = g_q_emb + (size_t)row * DD;
    const float* __restrict__ cv = g_cvec + (size_t)row * DD;

    float cpacc = 0.f;
#pragma unroll
    for (int i = 0; i < 8; i++) {
        const int d = l + 32 * i;
        float qv = qe[d];
        float cvv = cv[d];
        qsh[w][d] = qv;
        cpacc += qv * wcp[d] + cvv * wcp[DD + d];
    }
    __syncwarp();
#pragma unroll
    for (int s = 16; s > 0; s >>= 1) cpacc += __shfl_down_sync(0xffffffffu, cpacc, s);
    const float logit = __shfl_sync(0xffffffffu, cpacc, 0) + bcp[0];

    float g = (l < C1) ? bgen[l] : -INFINITY;
    if (l < C1) {
#pragma unroll 4
        for (int d = 0; d < DD; d++) g += qsh[w][d] * wg[d * C1 + l];
    }
    float mx = g;
#pragma unroll
    for (int s = 16; s > 0; s >>= 1) mx = fmaxf(mx, __shfl_xor_sync(0xffffffffu, mx, s));
    float ex = (l < C1) ? __expf(g - mx) : 0.f;
    float sum = ex;
#pragma unroll
    for (int s = 16; s > 0; s >>= 1) sum += __shfl_xor_sync(0xffffffffu, sum, s);
    const float lsm = g - mx - __logf(sum);

    if (l < C1) {
        const float cd = g_copy[(size_t)row * C1 + l];
        const float cp = -softplus_f(-logit);
        const float gp = -softplus_f(logit);
        const float a1 = cp + cd;
        const float a2 = gp + lsm;
        const float r = fmaxf(a1, a2);
        const float o = r + log1pf(__expf(fminf(a1, a2) - r));
        out[(size_t)row * C1 + l] = o;
    }
}

// =====================================================================
extern "C" void kernel_launch(void* const* d_in, const int* in_sizes, int n_in,
                              void* d_out, int out_size)
{
    const float* q_head = (const float*)d_in[0];
    const float* q_tail = (const float*)d_in[1];
    const float* c_head = (const float*)d_in[2];
    const float* c_tail = (const float*)d_in[3];
    const int*   labels = (const int*)d_in[4];
    const float* mask   = (const float*)d_in[5];
    const float* W_rel  = (const float*)d_in[6];
    const float* b_rel  = (const float*)d_in[7];
    const float* W_gen  = (const float*)d_in[8];
    const float* b_gen  = (const float*)d_in[9];
    const float* W_cp   = (const float*)d_in[10];
    const float* b_cp   = (const float*)d_in[11];
    float* out = (float*)d_out;

    cudaFuncSetAttribute(relemb_mma, cudaFuncAttributeMaxDynamicSharedMemorySize, GM_SMEM);
    cudaFuncSetAttribute(scores_mma, cudaFuncAttributeMaxDynamicSharedMemorySize, GM_SMEM);

    wconv_kernel<<<dim3(16, 8), dim3(32, 8)>>>(W_rel);
    relemb_mma<<<dim3(2, (BB * NQ) / 128), 256, GM_SMEM>>>(q_head, q_tail, b_rel, 0);
    relemb_mma<<<dim3(2, (BB * NC) / 128), 256, GM_SMEM>>>(c_head, c_tail, b_rel, 1);
    scores_mma<<<dim3(NC / 128, NQ / 128, BB), 256, GM_SMEM>>>(mask);  // launch idx 3 -> ncu capture
    reduce_cvec_kernel<<<dim3(NQ, BB), 256>>>(labels);
    final_kernel<<<(BB * NQ) / 8, 256>>>(W_gen, b_gen, W_cp, b_cp, out);
}

// round 12
// speedup vs baseline: 1.5442x; 1.5442x over previous
#include <cuda_runtime.h>
#include <cuda_bf16.h>
#include <math.h>
#include <stdint.h>

#define BB 8
#define NQ 1024
#define NC 4096
#define DD 256
#define C1 25
#define CAP 2048          // compacted survivors cap (expected ~15 per row)
#define THRESH 1e-9f      // e = exp(s-max) threshold; dropped mass < 4096e-9

// ---------------- scratch (static device globals; no allocation) ----------------
__device__ float g_q_emb[(size_t)BB * NQ * DD];            //  8 MB fp32 (final gate)
__device__ float g_scores[(size_t)BB * NQ * NC];           // 134 MB
__device__ float g_copy[(size_t)BB * NQ * C1];
__device__ float g_cvec[(size_t)BB * NQ * DD];
// bf16 split operands
__device__ __nv_bfloat16 g_qh[(size_t)BB * NQ * DD];
__device__ __nv_bfloat16 g_ql[(size_t)BB * NQ * DD];
__device__ __nv_bfloat16 g_ch[(size_t)BB * NC * DD];
__device__ __nv_bfloat16 g_cl[(size_t)BB * NC * DD];
__device__ __nv_bfloat16 g_wth[DD * 2 * DD];               // W_rel^T [256][512]
__device__ __nv_bfloat16 g_wtl[DD * 2 * DD];

// ---------------- helpers ----------------
__device__ __forceinline__ uint32_t smem_u32(const void* p) {
    uint32_t a;
    asm("{ .reg .u64 t; cvta.to.shared.u64 t, %1; cvt.u32.u64 %0, t; }" : "=r"(a) : "l"(p));
    return a;
}
static __device__ __forceinline__ uint32_t swz(uint32_t off) { return off ^ ((off >> 3) & 0x70); }

__device__ __forceinline__ unsigned pk2(float a, float b) {
    __nv_bfloat162 t = __floats2bfloat162_rn(a, b);
    return *reinterpret_cast<unsigned*>(&t);
}

__device__ __forceinline__ void ldmx4(uint32_t* r, uint32_t addr) {
    asm volatile("ldmatrix.sync.aligned.m8n8.x4.shared.b16 {%0,%1,%2,%3}, [%4];"
                 : "=r"(r[0]), "=r"(r[1]), "=r"(r[2]), "=r"(r[3]) : "r"(addr));
}
__device__ __forceinline__ void mma16816(float* d, const uint32_t* a, const uint32_t* b) {
    asm volatile(
        "mma.sync.aligned.m16n8k16.row.col.f32.bf16.bf16.f32 "
        "{%0,%1,%2,%3}, {%4,%5,%6,%7}, {%8,%9}, {%0,%1,%2,%3};"
        : "+f"(d[0]), "+f"(d[1]), "+f"(d[2]), "+f"(d[3])
        : "r"(a[0]), "r"(a[1]), "r"(a[2]), "r"(a[3]), "r"(b[0]), "r"(b[1]));
}
__device__ __forceinline__ void cp16(uint32_t dst, const void* src) {
    asm volatile("cp.async.cg.shared.global [%0], [%1], 16;" :: "r"(dst), "l"(src));
}
__device__ __forceinline__ void cp_commit() {
    asm volatile("cp.async.commit_group;");
}
template <int N>
__device__ __forceinline__ void cp_wait() {
    asm volatile("cp.async.wait_group %0;" :: "n"(N));
}

// async copy a bf16 tile [rows][64] from global (stride elems) into swizzled SMEM (128B rows)
__device__ __forceinline__ void copy_tile_async(uint32_t dst, const __nv_bfloat16* src,
                                                size_t stride, int rows, int tid, int nthr) {
    const int tasks = rows * 8;
    for (int t = tid; t < tasks; t += nthr) {
        const int r = t >> 3, g = t & 7;
        cp16(dst + swz((uint32_t)r * 128 + g * 16), src + (size_t)r * stride + g * 8);
    }
}

// tile offsets (single stage, BM=128, BK=64)
#define T_AH 0
#define T_AL (16 * 1024)
#define T_BH (32 * 1024)
#define T_BL (48 * 1024)
#define GM_SMEM (64 * 1024 + 1024)

// shared compute core: one BK=64 chunk; warp covers (MI*16) rows x 64 cols
template <int MI>
__device__ __forceinline__ void mma_chunkT(uint32_t base, uint32_t AH, uint32_t AL,
                                           uint32_t BH, uint32_t BL,
                                           int wm, int wn, int lane, float acc[][8][4]) {
    const int a_r = wm * (MI * 16) + (lane & 15);
    const int a_cb = ((lane >> 4) & 1) * 16;
    const int b_r = wn * 64 + (lane & 7) + ((lane >> 4) & 1) * 8;
    const int b_cb = ((lane >> 3) & 1) * 16;
#pragma unroll
    for (int ks = 0; ks < 4; ks++) {
        uint32_t ah[MI][4], al[MI][4];
#pragma unroll
        for (int mi = 0; mi < MI; mi++) {
            const uint32_t oA = swz((uint32_t)(a_r + mi * 16) * 128 + ks * 32 + a_cb);
            ldmx4(ah[mi], base + AH + oA);
            ldmx4(al[mi], base + AL + oA);
        }
#pragma unroll
        for (int p = 0; p < 4; p++) {
            const uint32_t oB = swz((uint32_t)(b_r + p * 16) * 128 + ks * 32 + b_cb);
            uint32_t bh[4], bl[4];
            ldmx4(bh, base + BH + oB);
            ldmx4(bl, base + BL + oB);
#pragma unroll
            for (int t = 0; t < 2; t++) {
                const int ni = p * 2 + t;
#pragma unroll
                for (int mi = 0; mi < MI; mi++) {
                    mma16816(acc[mi][ni], ah[mi], bh + t * 2);
                    mma16816(acc[mi][ni], ah[mi], bl + t * 2);
                    mma16816(acc[mi][ni], al[mi], bh + t * 2);
                }
            }
        }
    }
}

// =====================================================================
// Kernel 0: W_rel [512][256] -> W^T bf16 hi/lo [256][512]
// =====================================================================
__global__ void wconv_kernel(const float* __restrict__ W) {
    __shared__ float t[32][33];
    const int k0 = blockIdx.x * 32, n0 = blockIdx.y * 32;
    const int tx = threadIdx.x, ty = threadIdx.y;
#pragma unroll
    for (int i = 0; i < 4; i++)
        t[ty + 8 * i][tx] = W[(size_t)(k0 + ty + 8 * i) * 256 + n0 + tx];
    __syncthreads();
#pragma unroll
    for (int i = 0; i < 4; i++) {
        const int n = n0 + ty + 8 * i, k = k0 + tx;
        const float x = t[tx][ty + 8 * i];
        const __nv_bfloat16 h = __float2bfloat16_rn(x);
        g_wth[(size_t)n * 512 + k] = h;
        g_wtl[(size_t)n * 512 + k] = __float2bfloat16_rn(x - __bfloat162float(h));
    }
}

// =====================================================================
// Kernel 1: rel_emb (BM=128, K=512, 8 BK=64 chunks, single stage, 2 CTAs/SM)
// =====================================================================
__global__ __launch_bounds__(256, 2)
void relemb_mma(const float* __restrict__ H, const float* __restrict__ T,
                const float* __restrict__ bias, int is_c)
{
    extern __shared__ char dsm[];
    __shared__ float s_b[128];
    const uint32_t dbase = smem_u32(dsm);
    const uint32_t base = (dbase + 1023) & ~1023u;
    char* tp = dsm + (base - dbase);

    const int tid = threadIdx.x, wid = tid >> 5, lane = tid & 31;
    const int wm = wid >> 1, wn = wid & 1;
    const int n0 = blockIdx.x * 128, m0 = blockIdx.y * 128;
    if (tid < 128) s_b[tid] = bias[n0 + tid];

    float acc[2][8][4];
#pragma unroll
    for (int i = 0; i < 2; i++)
#pragma unroll
        for (int j = 0; j < 8; j++)
#pragma unroll
            for (int q = 0; q < 4; q++) acc[i][j][q] = 0.f;

    for (int kc = 0; kc < 8; kc++) {
        const float* src = (kc < 4) ? H : T;
        const int cb = (kc * 64) & 255;
        // B tiles via cp.async
        copy_tile_async(base + T_BH, g_wth + (size_t)n0 * 512 + kc * 64, 512, 128, tid, 256);
        copy_tile_async(base + T_BL, g_wtl + (size_t)n0 * 512 + kc * 64, 512, 128, tid, 256);
        cp_commit();
        // A: fp32 -> bf16 hi/lo split, swizzled (manual stores)
        for (int t = tid; t < 1024; t += 256) {
            const int r = t >> 3, g = t & 7;
            const float* s = src + (size_t)(m0 + r) * 256 + cb + g * 8;
            float4 x0 = *(const float4*)s;
            float4 x1 = *(const float4*)(s + 4);
            float xs[8] = {x0.x, x0.y, x0.z, x0.w, x1.x, x1.y, x1.z, x1.w};
            float h[8], l[8];
#pragma unroll
            for (int i = 0; i < 8; i++) {
                h[i] = __bfloat162float(__float2bfloat16_rn(xs[i]));
                l[i] = xs[i] - h[i];
            }
            const uint32_t off = swz((uint32_t)r * 128 + g * 16);
            *(uint4*)(tp + T_AH + off) = make_uint4(pk2(h[0], h[1]), pk2(h[2], h[3]), pk2(h[4], h[5]), pk2(h[6], h[7]));
            *(uint4*)(tp + T_AL + off) = make_uint4(pk2(l[0], l[1]), pk2(l[2], l[3]), pk2(l[4], l[5]), pk2(l[6], l[7]));
        }
        cp_wait<0>();
        __syncthreads();
        mma_chunkT<2>(base, T_AH, T_AL, T_BH, T_BL, wm, wn, lane, acc);
        __syncthreads();
    }

    // epilogue
    const int cbase = wn * 64 + (lane & 3) * 2;
    __nv_bfloat16* dh = is_c ? g_ch : g_qh;
    __nv_bfloat16* dl = is_c ? g_cl : g_ql;
#pragma unroll
    for (int mi = 0; mi < 2; mi++) {
        const int r = m0 + wm * 32 + mi * 16 + (lane >> 2);
#pragma unroll
        for (int ni = 0; ni < 8; ni++) {
            const int c = n0 + cbase + ni * 8;
            const float b0 = s_b[c - n0], b1 = s_b[c - n0 + 1];
#pragma unroll
            for (int hh = 0; hh < 2; hh++) {
                const int row = r + hh * 8;
                const float v0 = acc[mi][ni][hh * 2 + 0] + b0;
                const float v1 = acc[mi][ni][hh * 2 + 1] + b1;
                const float h0 = __bfloat162float(__float2bfloat16_rn(v0));
                const float h1 = __bfloat162float(__float2bfloat16_rn(v1));
                *(unsigned*)(dh + (size_t)row * 256 + c) = pk2(h0, h1);
                *(unsigned*)(dl + (size_t)row * 256 + c) = pk2(v0 - h0, v1 - h1);
                if (!is_c)
                    *(float2*)(g_q_emb + (size_t)row * 256 + c) = make_float2(v0, v1);
            }
        }
    }
}

// =====================================================================
// Kernel 2: scores = (Qe @ Ce^T) * mask (BM=128, 4 BK=64 chunks,
//           single stage, 2 CTAs/SM)
// =====================================================================
__global__ __launch_bounds__(256, 2)
void scores_mma(const float* __restrict__ mask)
{
    extern __shared__ char dsm[];
    __shared__ float s_msk[128];
    const uint32_t dbase = smem_u32(dsm);
    const uint32_t base = (dbase + 1023) & ~1023u;

    const int tid = threadIdx.x, wid = tid >> 5, lane = tid & 31;
    const int wm = wid >> 1, wn = wid & 1;
    const int n0 = blockIdx.x * 128, m0 = blockIdx.y * 128, b = blockIdx.z;
    if (tid < 128) s_msk[tid] = mask[(size_t)b * NC + n0 + tid];

    const __nv_bfloat16* qh = g_qh + ((size_t)b * NQ + m0) * 256;
    const __nv_bfloat16* ql = g_ql + ((size_t)b * NQ + m0) * 256;
    const __nv_bfloat16* ch = g_ch + ((size_t)b * NC + n0) * 256;
    const __nv_bfloat16* cl = g_cl + ((size_t)b * NC + n0) * 256;

    float acc[2][8][4];
#pragma unroll
    for (int i = 0; i < 2; i++)
#pragma unroll
        for (int j = 0; j < 8; j++)
#pragma unroll
            for (int q = 0; q < 4; q++) acc[i][j][q] = 0.f;

    for (int kc = 0; kc < 4; kc++) {
        const int k0 = kc * 64;
        copy_tile_async(base + T_AH, qh + k0, 256, 128, tid, 256);
        copy_tile_async(base + T_AL, ql + k0, 256, 128, tid, 256);
        copy_tile_async(base + T_BH, ch + k0, 256, 128, tid, 256);
        copy_tile_async(base + T_BL, cl + k0, 256, 128, tid, 256);
        cp_commit();
        cp_wait<0>();
        __syncthreads();
        mma_chunkT<2>(base, T_AH, T_AL, T_BH, T_BL, wm, wn, lane, acc);
        __syncthreads();
    }

    const int cbase = wn * 64 + (lane & 3) * 2;
#pragma unroll
    for (int mi = 0; mi < 2; mi++) {
        const int r = m0 + wm * 32 + mi * 16 + (lane >> 2);
#pragma unroll
        for (int ni = 0; ni < 8; ni++) {
            const int cl_ = cbase + ni * 8;
            const float mv0 = s_msk[cl_], mv1 = s_msk[cl_ + 1];
            float* p = g_scores + ((size_t)b * NQ + r) * NC + n0 + cl_;
            *(float2*)p = make_float2(acc[mi][ni][0] * mv0, acc[mi][ni][1] * mv1);
            *(float2*)(p + (size_t)8 * NC) = make_float2(acc[mi][ni][2] * mv0, acc[mi][ni][3] * mv1);
        }
    }
}

// =====================================================================
// Kernel 3: fused row softmax stats + class bins + SPARSE context_vec
//   - warp-shuffle max (1 barrier instead of 8)
//   - sub-banked bins[C1][8] indexed by tid&7 (cuts ATOMS same-addr
//     serialization ~4x -> ~1.1x)
// =====================================================================
__global__ __launch_bounds__(256)
void reduce_cvec_kernel(const int* __restrict__ labels)
{
    const int q = blockIdx.x, b = blockIdx.y;
    const size_t rowoff = ((size_t)b * NQ + q) * NC;
    const float* __restrict__ srow = g_scores + rowoff;
    const int* __restrict__ lab = labels + (size_t)b * NC;
    const int tid = threadIdx.x;
    const int lane = tid & 31, wid = tid >> 5;
    const int sub = tid & 7;

    __shared__ float wmax[8];
    __shared__ float bins2[C1][8];
    __shared__ float bins[C1];
    __shared__ float total_sh;
    __shared__ int s_idx[CAP];
    __shared__ float s_e[CAP];
    __shared__ int s_cnt;

    float4 vals[4];
    float m = -INFINITY;
#pragma unroll
    for (int i = 0; i < 4; i++) {
        vals[i] = *(const float4*)(srow + (size_t)(i * 256 + tid) * 4);
        m = fmaxf(m, fmaxf(fmaxf(vals[i].x, vals[i].y), fmaxf(vals[i].z, vals[i].w)));
    }
#pragma unroll
    for (int s = 16; s > 0; s >>= 1) m = fmaxf(m, __shfl_xor_sync(0xffffffffu, m, s));
    if (lane == 0) wmax[wid] = m;
    if (tid < C1 * 8) bins2[tid / 8][tid & 7] = 0.f;
    if (tid == 0) s_cnt = 0;
    __syncthreads();
    m = wmax[0];
#pragma unroll
    for (int w = 1; w < 8; w++) m = fmaxf(m, wmax[w]);

#pragma unroll
    for (int i = 0; i < 4; i++) {
        const int bpos = (i * 256 + tid) * 4;
        int4 lb = *(const int4*)(lab + bpos);
        float e0 = __expf(vals[i].x - m), e1 = __expf(vals[i].y - m);
        float e2 = __expf(vals[i].z - m), e3 = __expf(vals[i].w - m);
        atomicAdd(&bins2[lb.x][sub], e0);
        atomicAdd(&bins2[lb.y][sub], e1);
        atomicAdd(&bins2[lb.z][sub], e2);
        atomicAdd(&bins2[lb.w][sub], e3);
        float ee[4] = {e0, e1, e2, e3};
#pragma unroll
        for (int c = 0; c < 4; c++) {
            if (ee[c] > THRESH) {
                int p = atomicAdd(&s_cnt, 1);
                if (p < CAP) { s_idx[p] = bpos + c; s_e[p] = ee[c]; }
            }
        }
    }
    __syncthreads();
    if (tid < C1) {
        float v = 0.f;
#pragma unroll
        for (int s = 0; s < 8; s++) v += bins2[tid][s];
        bins[tid] = v;
    }
    __syncthreads();
    if (tid == 0) {
        float t = 0.f;
        for (int c = 0; c < C1; c++) t += bins[c];
        total_sh = t;
    }
    __syncthreads();

    // sparse context vector: d = tid
    {
        const __nv_bfloat16* chb = g_ch + (size_t)b * NC * DD;
        const __nv_bfloat16* clb = g_cl + (size_t)b * NC * DD;
        const int cnt = (s_cnt < CAP) ? s_cnt : CAP;
        float acc = 0.f;
        for (int i = 0; i < cnt; i++) {
            const size_t joff = (size_t)s_idx[i] * DD + tid;
            acc += s_e[i] * (__bfloat162float(chb[joff]) + __bfloat162float(clb[joff]));
        }
        g_cvec[((size_t)b * NQ + q) * DD + tid] = acc / total_sh;
    }

    if (tid < C1) {
        g_copy[((size_t)b * NQ + q) * C1 + tid] = __logf(bins[tid]) - __logf(total_sh);
    }
}

// =====================================================================
// Kernel 4: epilogue — gen log_softmax, gate, combine
// =====================================================================
__device__ __forceinline__ float softplus_f(float z) {
    return (z > 20.f) ? z : log1pf(__expf(z));
}

__global__ __launch_bounds__(256)
void final_kernel(const float* __restrict__ Wgen, const float* __restrict__ bgen,
                  const float* __restrict__ Wcp, const float* __restrict__ bcp,
                  float* __restrict__ out)
{
    __shared__ float wg[DD * C1];
    __shared__ float wcp[2 * DD];
    __shared__ float qsh[8][DD];
    const int tid = threadIdx.x;
    for (int i = tid; i < DD * C1; i += 256) wg[i] = Wgen[i];
    for (int i = tid; i < 2 * DD; i += 256) wcp[i] = Wcp[i];
    __syncthreads();

    const int w = tid >> 5, l = tid & 31;
    const int row = blockIdx.x * 8 + w;
    const float* __restrict__ qe = g_q_emb + (size_t)row * DD;
    const float* __restrict__ cv = g_cvec + (size_t)row * DD;

    float cpacc = 0.f;
#pragma unroll
    for (int i = 0; i < 8; i++) {
        const int d = l + 32 * i;
        float qv = qe[d];
        float cvv = cv[d];
        qsh[w][d] = qv;
        cpacc += qv * wcp[d] + cvv * wcp[DD + d];
    }
    __syncwarp();
#pragma unroll
    for (int s = 16; s > 0; s >>= 1) cpacc += __shfl_down_sync(0xffffffffu, cpacc, s);
    const float logit = __shfl_sync(0xffffffffu, cpacc, 0) + bcp[0];

    float g = (l < C1) ? bgen[l] : -INFINITY;
    if (l < C1) {
#pragma unroll 4
        for (int d = 0; d < DD; d++) g += qsh[w][d] * wg[d * C1 + l];
    }
    float mx = g;
#pragma unroll
    for (int s = 16; s > 0; s >>= 1) mx = fmaxf(mx, __shfl_xor_sync(0xffffffffu, mx, s));
    float ex = (l < C1) ? __expf(g - mx) : 0.f;
    float sum = ex;
#pragma unroll
    for (int s = 16; s > 0; s >>= 1) sum += __shfl_xor_sync(0xffffffffu, sum, s);
    const float lsm = g - mx - __logf(sum);

    if (l < C1) {
        const float cd = g_copy[(size_t)row * C1 + l];
        const float cp = -softplus_f(-logit);
        const float gp = -softplus_f(logit);
        const float a1 = cp + cd;
        const float a2 = gp + lsm;
        const float r = fmaxf(a1, a2);
        const float o = r + log1pf(__expf(fminf(a1, a2) - r));
        out[(size_t)row * C1 + l] = o;
    }
}

// =====================================================================
extern "C" void kernel_launch(void* const* d_in, const int* in_sizes, int n_in,
                              void* d_out, int out_size)
{
    const float* q_head = (const float*)d_in[0];
    const float* q_tail = (const float*)d_in[1];
    const float* c_head = (const float*)d_in[2];
    const float* c_tail = (const float*)d_in[3];
    const int*   labels = (const int*)d_in[4];
    const float* mask   = (const float*)d_in[5];
    const float* W_rel  = (const float*)d_in[6];
    const float* b_rel  = (const float*)d_in[7];
    const float* W_gen  = (const float*)d_in[8];
    const float* b_gen  = (const float*)d_in[9];
    const float* W_cp   = (const float*)d_in[10];
    const float* b_cp   = (const float*)d_in[11];
    float* out = (float*)d_out;

    cudaFuncSetAttribute(relemb_mma, cudaFuncAttributeMaxDynamicSharedMemorySize, GM_SMEM);
    cudaFuncSetAttribute(scores_mma, cudaFuncAttributeMaxDynamicSharedMemorySize, GM_SMEM);

    wconv_kernel<<<dim3(16, 8), dim3(32, 8)>>>(W_rel);
    relemb_mma<<<dim3(2, (BB * NQ) / 128), 256, GM_SMEM>>>(q_head, q_tail, b_rel, 0);
    relemb_mma<<<dim3(2, (BB * NC) / 128), 256, GM_SMEM>>>(c_head, c_tail, b_rel, 1);
    scores_mma<<<dim3(NC / 128, NQ / 128, BB), 256, GM_SMEM>>>(mask);
    reduce_cvec_kernel<<<dim3(NQ, BB), 256>>>(labels);
    final_kernel<<<(BB * NQ) / 8, 256>>>(W_gen, b_gen, W_cp, b_cp, out);
}

// round 16
// speedup vs baseline: 1.5885x; 1.0287x over previous
#include <cuda_runtime.h>
#include <cuda_bf16.h>
#include <math.h>
#include <stdint.h>

#define BB 8
#define NQ 1024
#define NC 4096
#define DD 256
#define C1 25
#define CAP 2048          // compacted survivors cap (expected ~15 per row)
#define THRESH 1e-9f      // e = exp(s-max) threshold; dropped mass < 4096e-9

// ---------------- scratch (static device globals; no allocation) ----------------
__device__ float g_q_emb[(size_t)BB * NQ * DD];            //  8 MB fp32 (final gate)
__device__ float g_scores[(size_t)BB * NQ * NC];           // 134 MB
__device__ float g_copy[(size_t)BB * NQ * C1];
__device__ float g_cvec[(size_t)BB * NQ * DD];
// bf16 split operands
__device__ __nv_bfloat16 g_qh[(size_t)BB * NQ * DD];
__device__ __nv_bfloat16 g_ql[(size_t)BB * NQ * DD];
__device__ __nv_bfloat16 g_ch[(size_t)BB * NC * DD];
__device__ __nv_bfloat16 g_cl[(size_t)BB * NC * DD];
__device__ __nv_bfloat16 g_wth[DD * 2 * DD];               // W_rel^T [256][512]
__device__ __nv_bfloat16 g_wtl[DD * 2 * DD];

// ---------------- helpers ----------------
__device__ __forceinline__ uint32_t smem_u32(const void* p) {
    uint32_t a;
    asm("{ .reg .u64 t; cvta.to.shared.u64 t, %1; cvt.u32.u64 %0, t; }" : "=r"(a) : "l"(p));
    return a;
}
static __device__ __forceinline__ uint32_t swz(uint32_t off) { return off ^ ((off >> 3) & 0x70); }

__device__ __forceinline__ unsigned pk2(float a, float b) {
    __nv_bfloat162 t = __floats2bfloat162_rn(a, b);
    return *reinterpret_cast<unsigned*>(&t);
}

__device__ __forceinline__ void ldmx4(uint32_t* r, uint32_t addr) {
    asm volatile("ldmatrix.sync.aligned.m8n8.x4.shared.b16 {%0,%1,%2,%3}, [%4];"
                 : "=r"(r[0]), "=r"(r[1]), "=r"(r[2]), "=r"(r[3]) : "r"(addr));
}
__device__ __forceinline__ void mma16816(float* d, const uint32_t* a, const uint32_t* b) {
    asm volatile(
        "mma.sync.aligned.m16n8k16.row.col.f32.bf16.bf16.f32 "
        "{%0,%1,%2,%3}, {%4,%5,%6,%7}, {%8,%9}, {%0,%1,%2,%3};"
        : "+f"(d[0]), "+f"(d[1]), "+f"(d[2]), "+f"(d[3])
        : "r"(a[0]), "r"(a[1]), "r"(a[2]), "r"(a[3]), "r"(b[0]), "r"(b[1]));
}
__device__ __forceinline__ void cp16(uint32_t dst, const void* src) {
    asm volatile("cp.async.cg.shared.global [%0], [%1], 16;" :: "r"(dst), "l"(src));
}
__device__ __forceinline__ void cp_commit() {
    asm volatile("cp.async.commit_group;");
}
template <int N>
__device__ __forceinline__ void cp_wait() {
    asm volatile("cp.async.wait_group %0;" :: "n"(N));
}

// async copy a bf16 tile [rows][64] from global (stride elems) into swizzled SMEM (128B rows)
__device__ __forceinline__ void copy_tile_async(uint32_t dst, const __nv_bfloat16* src,
                                                size_t stride, int rows, int tid, int nthr) {
    const int tasks = rows * 8;
    for (int t = tid; t < tasks; t += nthr) {
        const int r = t >> 3, g = t & 7;
        cp16(dst + swz((uint32_t)r * 128 + g * 16), src + (size_t)r * stride + g * 8);
    }
}

// tile offsets (single stage, BM=128, BK=64)
#define T_AH 0
#define T_AL (16 * 1024)
#define T_BH (32 * 1024)
#define T_BL (48 * 1024)
#define GM_SMEM (64 * 1024 + 1024)

// shared compute core: one BK=64 chunk; warp covers (MI*16) rows x 64 cols
template <int MI>
__device__ __forceinline__ void mma_chunkT(uint32_t base, uint32_t AH, uint32_t AL,
                                           uint32_t BH, uint32_t BL,
                                           int wm, int wn, int lane, float acc[][8][4]) {
    const int a_r = wm * (MI * 16) + (lane & 15);
    const int a_cb = ((lane >> 4) & 1) * 16;
    const int b_r = wn * 64 + (lane & 7) + ((lane >> 4) & 1) * 8;
    const int b_cb = ((lane >> 3) & 1) * 16;
#pragma unroll
    for (int ks = 0; ks < 4; ks++) {
        uint32_t ah[MI][4], al[MI][4];
#pragma unroll
        for (int mi = 0; mi < MI; mi++) {
            const uint32_t oA = swz((uint32_t)(a_r + mi * 16) * 128 + ks * 32 + a_cb);
            ldmx4(ah[mi], base + AH + oA);
            ldmx4(al[mi], base + AL + oA);
        }
#pragma unroll
        for (int p = 0; p < 4; p++) {
            const uint32_t oB = swz((uint32_t)(b_r + p * 16) * 128 + ks * 32 + b_cb);
            uint32_t bh[4], bl[4];
            ldmx4(bh, base + BH + oB);
            ldmx4(bl, base + BL + oB);
#pragma unroll
            for (int t = 0; t < 2; t++) {
                const int ni = p * 2 + t;
#pragma unroll
                for (int mi = 0; mi < MI; mi++) {
                    mma16816(acc[mi][ni], ah[mi], bh + t * 2);
                    mma16816(acc[mi][ni], ah[mi], bl + t * 2);
                    mma16816(acc[mi][ni], al[mi], bh + t * 2);
                }
            }
        }
    }
}

// =====================================================================
// Kernel 0: W_rel [512][256] -> W^T bf16 hi/lo [256][512]
// =====================================================================
__global__ void wconv_kernel(const float* __restrict__ W) {
    __shared__ float t[32][33];
    const int k0 = blockIdx.x * 32, n0 = blockIdx.y * 32;
    const int tx = threadIdx.x, ty = threadIdx.y;
#pragma unroll
    for (int i = 0; i < 4; i++)
        t[ty + 8 * i][tx] = W[(size_t)(k0 + ty + 8 * i) * 256 + n0 + tx];
    __syncthreads();
#pragma unroll
    for (int i = 0; i < 4; i++) {
        const int n = n0 + ty + 8 * i, k = k0 + tx;
        const float x = t[tx][ty + 8 * i];
        const __nv_bfloat16 h = __float2bfloat16_rn(x);
        g_wth[(size_t)n * 512 + k] = h;
        g_wtl[(size_t)n * 512 + k] = __float2bfloat16_rn(x - __bfloat162float(h));
    }
}

// =====================================================================
// Kernel 1: rel_emb MERGED (q tiles + c tiles in one launch)
// grid (2, 64 + 256); blockIdx.y < 64 -> q rows, else c rows
// BM=128, K=512, 8 BK=64 chunks, single stage, 2 CTAs/SM
// =====================================================================
__global__ __launch_bounds__(256, 2)
void relemb_all(const float* __restrict__ QH, const float* __restrict__ QT,
                const float* __restrict__ CH, const float* __restrict__ CT,
                const float* __restrict__ bias)
{
    extern __shared__ char dsm[];
    __shared__ float s_b[128];
    const uint32_t dbase = smem_u32(dsm);
    const uint32_t base = (dbase + 1023) & ~1023u;
    char* tp = dsm + (base - dbase);

    const int tid = threadIdx.x, wid = tid >> 5, lane = tid & 31;
    const int wm = wid >> 1, wn = wid & 1;
    const int n0 = blockIdx.x * 128;
    const int ty = blockIdx.y;
    const int QTILES = (BB * NQ) / 128;  // 64
    const int is_c = (ty >= QTILES);
    const float* H = is_c ? CH : QH;
    const float* T = is_c ? CT : QT;
    const int m0 = (is_c ? (ty - QTILES) : ty) * 128;
    if (tid < 128) s_b[tid] = bias[n0 + tid];

    float acc[2][8][4];
#pragma unroll
    for (int i = 0; i < 2; i++)
#pragma unroll
        for (int j = 0; j < 8; j++)
#pragma unroll
            for (int q = 0; q < 4; q++) acc[i][j][q] = 0.f;

    for (int kc = 0; kc < 8; kc++) {
        const float* src = (kc < 4) ? H : T;
        const int cb = (kc * 64) & 255;
        copy_tile_async(base + T_BH, g_wth + (size_t)n0 * 512 + kc * 64, 512, 128, tid, 256);
        copy_tile_async(base + T_BL, g_wtl + (size_t)n0 * 512 + kc * 64, 512, 128, tid, 256);
        cp_commit();
        for (int t = tid; t < 1024; t += 256) {
            const int r = t >> 3, g = t & 7;
            const float* s = src + (size_t)(m0 + r) * 256 + cb + g * 8;
            float4 x0 = *(const float4*)s;
            float4 x1 = *(const float4*)(s + 4);
            float xs[8] = {x0.x, x0.y, x0.z, x0.w, x1.x, x1.y, x1.z, x1.w};
            float h[8], l[8];
#pragma unroll
            for (int i = 0; i < 8; i++) {
                h[i] = __bfloat162float(__float2bfloat16_rn(xs[i]));
                l[i] = xs[i] - h[i];
            }
            const uint32_t off = swz((uint32_t)r * 128 + g * 16);
            *(uint4*)(tp + T_AH + off) = make_uint4(pk2(h[0], h[1]), pk2(h[2], h[3]), pk2(h[4], h[5]), pk2(h[6], h[7]));
            *(uint4*)(tp + T_AL + off) = make_uint4(pk2(l[0], l[1]), pk2(l[2], l[3]), pk2(l[4], l[5]), pk2(l[6], l[7]));
        }
        cp_wait<0>();
        __syncthreads();
        mma_chunkT<2>(base, T_AH, T_AL, T_BH, T_BL, wm, wn, lane, acc);
        __syncthreads();
    }

    // epilogue
    const int cbase = wn * 64 + (lane & 3) * 2;
    __nv_bfloat16* dh = is_c ? g_ch : g_qh;
    __nv_bfloat16* dl = is_c ? g_cl : g_ql;
#pragma unroll
    for (int mi = 0; mi < 2; mi++) {
        const int r = m0 + wm * 32 + mi * 16 + (lane >> 2);
#pragma unroll
        for (int ni = 0; ni < 8; ni++) {
            const int c = n0 + cbase + ni * 8;
            const float b0 = s_b[c - n0], b1 = s_b[c - n0 + 1];
#pragma unroll
            for (int hh = 0; hh < 2; hh++) {
                const int row = r + hh * 8;
                const float v0 = acc[mi][ni][hh * 2 + 0] + b0;
                const float v1 = acc[mi][ni][hh * 2 + 1] + b1;
                const float h0 = __bfloat162float(__float2bfloat16_rn(v0));
                const float h1 = __bfloat162float(__float2bfloat16_rn(v1));
                *(unsigned*)(dh + (size_t)row * 256 + c) = pk2(h0, h1);
                *(unsigned*)(dl + (size_t)row * 256 + c) = pk2(v0 - h0, v1 - h1);
                if (!is_c)
                    *(float2*)(g_q_emb + (size_t)row * 256 + c) = make_float2(v0, v1);
            }
        }
    }
}

// =====================================================================
// Kernel 2: scores = (Qe @ Ce^T) * mask (BM=128, 4 BK=64 chunks,
//           single stage, 2 CTAs/SM)
// =====================================================================
__global__ __launch_bounds__(256, 2)
void scores_mma(const float* __restrict__ mask)
{
    extern __shared__ char dsm[];
    __shared__ float s_msk[128];
    const uint32_t dbase = smem_u32(dsm);
    const uint32_t base = (dbase + 1023) & ~1023u;

    const int tid = threadIdx.x, wid = tid >> 5, lane = tid & 31;
    const int wm = wid >> 1, wn = wid & 1;
    const int n0 = blockIdx.x * 128, m0 = blockIdx.y * 128, b = blockIdx.z;
    if (tid < 128) s_msk[tid] = mask[(size_t)b * NC + n0 + tid];

    const __nv_bfloat16* qh = g_qh + ((size_t)b * NQ + m0) * 256;
    const __nv_bfloat16* ql = g_ql + ((size_t)b * NQ + m0) * 256;
    const __nv_bfloat16* ch = g_ch + ((size_t)b * NC + n0) * 256;
    const __nv_bfloat16* cl = g_cl + ((size_t)b * NC + n0) * 256;

    float acc[2][8][4];
#pragma unroll
    for (int i = 0; i < 2; i++)
#pragma unroll
        for (int j = 0; j < 8; j++)
#pragma unroll
            for (int q = 0; q < 4; q++) acc[i][j][q] = 0.f;

    for (int kc = 0; kc < 4; kc++) {
        const int k0 = kc * 64;
        copy_tile_async(base + T_AH, qh + k0, 256, 128, tid, 256);
        copy_tile_async(base + T_AL, ql + k0, 256, 128, tid, 256);
        copy_tile_async(base + T_BH, ch + k0, 256, 128, tid, 256);
        copy_tile_async(base + T_BL, cl + k0, 256, 128, tid, 256);
        cp_commit();
        cp_wait<0>();
        __syncthreads();
        mma_chunkT<2>(base, T_AH, T_AL, T_BH, T_BL, wm, wn, lane, acc);
        __syncthreads();
    }

    const int cbase = wn * 64 + (lane & 3) * 2;
#pragma unroll
    for (int mi = 0; mi < 2; mi++) {
        const int r = m0 + wm * 32 + mi * 16 + (lane >> 2);
#pragma unroll
        for (int ni = 0; ni < 8; ni++) {
            const int cl_ = cbase + ni * 8;
            const float mv0 = s_msk[cl_], mv1 = s_msk[cl_ + 1];
            float* p = g_scores + ((size_t)b * NQ + r) * NC + n0 + cl_;
            *(float2*)p = make_float2(acc[mi][ni][0] * mv0, acc[mi][ni][1] * mv1);
            *(float2*)(p + (size_t)8 * NC) = make_float2(acc[mi][ni][2] * mv0, acc[mi][ni][3] * mv1);
        }
    }
}

// =====================================================================
// Kernel 3: fused row softmax stats + class bins + SPARSE context_vec
//   (proven R12 version: warp-shuffle max, sub-banked bins)
// =====================================================================
__global__ __launch_bounds__(256)
void reduce_cvec_kernel(const int* __restrict__ labels)
{
    const int q = blockIdx.x, b = blockIdx.y;
    const size_t rowoff = ((size_t)b * NQ + q) * NC;
    const float* __restrict__ srow = g_scores + rowoff;
    const int* __restrict__ lab = labels + (size_t)b * NC;
    const int tid = threadIdx.x;
    const int lane = tid & 31, wid = tid >> 5;
    const int sub = tid & 7;

    __shared__ float wmax[8];
    __shared__ float bins2[C1][8];
    __shared__ float bins[C1];
    __shared__ float total_sh;
    __shared__ int s_idx[CAP];
    __shared__ float s_e[CAP];
    __shared__ int s_cnt;

    float4 vals[4];
    float m = -INFINITY;
#pragma unroll
    for (int i = 0; i < 4; i++) {
        vals[i] = *(const float4*)(srow + (size_t)(i * 256 + tid) * 4);
        m = fmaxf(m, fmaxf(fmaxf(vals[i].x, vals[i].y), fmaxf(vals[i].z, vals[i].w)));
    }
#pragma unroll
    for (int s = 16; s > 0; s >>= 1) m = fmaxf(m, __shfl_xor_sync(0xffffffffu, m, s));
    if (lane == 0) wmax[wid] = m;
    if (tid < C1 * 8) bins2[tid / 8][tid & 7] = 0.f;
    if (tid == 0) s_cnt = 0;
    __syncthreads();
    m = wmax[0];
#pragma unroll
    for (int w = 1; w < 8; w++) m = fmaxf(m, wmax[w]);

#pragma unroll
    for (int i = 0; i < 4; i++) {
        const int bpos = (i * 256 + tid) * 4;
        int4 lb = *(const int4*)(lab + bpos);
        float e0 = __expf(vals[i].x - m), e1 = __expf(vals[i].y - m);
        float e2 = __expf(vals[i].z - m), e3 = __expf(vals[i].w - m);
        atomicAdd(&bins2[lb.x][sub], e0);
        atomicAdd(&bins2[lb.y][sub], e1);
        atomicAdd(&bins2[lb.z][sub], e2);
        atomicAdd(&bins2[lb.w][sub], e3);
        float ee[4] = {e0, e1, e2, e3};
#pragma unroll
        for (int c = 0; c < 4; c++) {
            if (ee[c] > THRESH) {
                int p = atomicAdd(&s_cnt, 1);
                if (p < CAP) { s_idx[p] = bpos + c; s_e[p] = ee[c]; }
            }
        }
    }
    __syncthreads();
    if (tid < C1) {
        float v = 0.f;
#pragma unroll
        for (int s = 0; s < 8; s++) v += bins2[tid][s];
        bins[tid] = v;
    }
    __syncthreads();
    if (tid == 0) {
        float t = 0.f;
        for (int c = 0; c < C1; c++) t += bins[c];
        total_sh = t;
    }
    __syncthreads();

    // sparse context vector: d = tid (unroll 2 for load ILP)
    {
        const __nv_bfloat16* chb = g_ch + (size_t)b * NC * DD;
        const __nv_bfloat16* clb = g_cl + (size_t)b * NC * DD;
        const int cnt = (s_cnt < CAP) ? s_cnt : CAP;
        float acc = 0.f;
        int i = 0;
        for (; i + 1 < cnt; i += 2) {
            const size_t j0 = (size_t)s_idx[i] * DD + tid;
            const size_t j1 = (size_t)s_idx[i + 1] * DD + tid;
            const float a0 = __bfloat162float(chb[j0]) + __bfloat162float(clb[j0]);
            const float a1 = __bfloat162float(chb[j1]) + __bfloat162float(clb[j1]);
            acc += s_e[i] * a0 + s_e[i + 1] * a1;
        }
        if (i < cnt) {
            const size_t j0 = (size_t)s_idx[i] * DD + tid;
            acc += s_e[i] * (__bfloat162float(chb[j0]) + __bfloat162float(clb[j0]));
        }
        g_cvec[((size_t)b * NQ + q) * DD + tid] = acc / total_sh;
    }

    if (tid < C1) {
        g_copy[((size_t)b * NQ + q) * C1 + tid] = __logf(bins[tid]) - __logf(total_sh);
    }
}

// =====================================================================
// Kernel 4: epilogue — gen log_softmax, gate, combine
// =====================================================================
__device__ __forceinline__ float softplus_f(float z) {
    return (z > 20.f) ? z : log1pf(__expf(z));
}

__global__ __launch_bounds__(256)
void final_kernel(const float* __restrict__ Wgen, const float* __restrict__ bgen,
                  const float* __restrict__ Wcp, const float* __restrict__ bcp,
                  float* __restrict__ out)
{
    __shared__ float wg[DD * C1];
    __shared__ float wcp[2 * DD];
    __shared__ float qsh[8][DD];
    const int tid = threadIdx.x;
    for (int i = tid; i < DD * C1; i += 256) wg[i] = Wgen[i];
    for (int i = tid; i < 2 * DD; i += 256) wcp[i] = Wcp[i];
    __syncthreads();

    const int w = tid >> 5, l = tid & 31;
    const int row = blockIdx.x * 8 + w;
    const float* __restrict__ qe = g_q_emb + (size_t)row * DD;
    const float* __restrict__ cv = g_cvec + (size_t)row * DD;

    float cpacc = 0.f;
#pragma unroll
    for (int i = 0; i < 8; i++) {
        const int d = l + 32 * i;
        float qv = qe[d];
        float cvv = cv[d];
        qsh[w][d] = qv;
        cpacc += qv * wcp[d] + cvv * wcp[DD + d];
    }
    __syncwarp();
#pragma unroll
    for (int s = 16; s > 0; s >>= 1) cpacc += __shfl_down_sync(0xffffffffu, cpacc, s);
    const float logit = __shfl_sync(0xffffffffu, cpacc, 0) + bcp[0];

    float g = (l < C1) ? bgen[l] : -INFINITY;
    if (l < C1) {
#pragma unroll 4
        for (int d = 0; d < DD; d++) g += qsh[w][d] * wg[d * C1 + l];
    }
    float mx = g;
#pragma unroll
    for (int s = 16; s > 0; s >>= 1) mx = fmaxf(mx, __shfl_xor_sync(0xffffffffu, mx, s));
    float ex = (l < C1) ? __expf(g - mx) : 0.f;
    float sum = ex;
#pragma unroll
    for (int s = 16; s > 0; s >>= 1) sum += __shfl_xor_sync(0xffffffffu, sum, s);
    const float lsm = g - mx - __logf(sum);

    if (l < C1) {
        const float cd = g_copy[(size_t)row * C1 + l];
        const float cp = -softplus_f(-logit);
        const float gp = -softplus_f(logit);
        const float a1 = cp + cd;
        const float a2 = gp + lsm;
        const float r = fmaxf(a1, a2);
        const float o = r + log1pf(__expf(fminf(a1, a2) - r));
        out[(size_t)row * C1 + l] = o;
    }
}

// =====================================================================
extern "C" void kernel_launch(void* const* d_in, const int* in_sizes, int n_in,
                              void* d_out, int out_size)
{
    const float* q_head = (const float*)d_in[0];
    const float* q_tail = (const float*)d_in[1];
    const float* c_head = (const float*)d_in[2];
    const float* c_tail = (const float*)d_in[3];
    const int*   labels = (const int*)d_in[4];
    const float* mask   = (const float*)d_in[5];
    const float* W_rel  = (const float*)d_in[6];
    const float* b_rel  = (const float*)d_in[7];
    const float* W_gen  = (const float*)d_in[8];
    const float* b_gen  = (const float*)d_in[9];
    const float* W_cp   = (const float*)d_in[10];
    const float* b_cp   = (const float*)d_in[11];
    float* out = (float*)d_out;

    cudaFuncSetAttribute(relemb_all, cudaFuncAttributeMaxDynamicSharedMemorySize, GM_SMEM);
    cudaFuncSetAttribute(scores_mma, cudaFuncAttributeMaxDynamicSharedMemorySize, GM_SMEM);

    wconv_kernel<<<dim3(16, 8), dim3(32, 8)>>>(W_rel);
    relemb_all<<<dim3(2, (BB * NQ) / 128 + (BB * NC) / 128), 256, GM_SMEM>>>(
        q_head, q_tail, c_head, c_tail, b_rel);
    scores_mma<<<dim3(NC / 128, NQ / 128, BB), 256, GM_SMEM>>>(mask);
    reduce_cvec_kernel<<<dim3(NQ, BB), 256>>>(labels);
    final_kernel<<<(BB * NQ) / 8, 256>>>(W_gen, b_gen, W_cp, b_cp, out);
}